// round 3
// baseline (speedup 1.0000x reference)
#include <cuda_runtime.h>
#include <cuda_bf16.h>

#define M_TOTAL 65536   // B*T = 512*128
#define C_DIM   384
#define H_DIM   64
#define T_DIM   128
#define B_DIM   512
#define SROW    68      // smem row stride (pad 64 -> 68): float4-aligned, conflict-free

// Scratch for Q, K, V planes: 3 * 65536 * 64 * 4B = 50.3 MB (static device array — allowed)
__device__ float g_qkv[3u * M_TOTAL * H_DIM];

// ---------------------------------------------------------------------------
// Kernel A: QKV projection GEMM. C[plane] = x @ W[plane]
// x: [65536, 384] row-major, W: [384, 64] row-major.
// Tile: BM=128, BN=64 (full H), BK=16; 256 threads; 8x4 register tile/thread.
// ---------------------------------------------------------------------------
__global__ __launch_bounds__(256) void qkv_gemm_kernel(
    const float* __restrict__ x,
    const float* __restrict__ Wq,
    const float* __restrict__ Wk,
    const float* __restrict__ Wv)
{
    constexpr int BM = 128, BN = 64, BK = 16;
    __shared__ float As[BK][BM + 4];   // transposed A tile, padded
    __shared__ float Bs[BK][BN];

    const int plane = blockIdx.y;
    const float* __restrict__ W = (plane == 0) ? Wq : (plane == 1) ? Wk : Wv;
    const int m0  = blockIdx.x * BM;
    const int tid = threadIdx.x;
    const int tx  = tid & 15;   // n: 4 outputs each -> 64
    const int ty  = tid >> 4;   // m: 8 outputs each -> 128

    float acc[8][4];
    #pragma unroll
    for (int i = 0; i < 8; i++)
        #pragma unroll
        for (int j = 0; j < 4; j++) acc[i][j] = 0.f;

    for (int k0 = 0; k0 < C_DIM; k0 += BK) {
        // Load A tile 128x16 (512 float4, 2 per thread), store transposed As[k][m]
        #pragma unroll
        for (int i = 0; i < 2; i++) {
            int idx = tid + i * 256;
            int r = idx >> 2;             // 0..127
            int c = (idx & 3) << 2;       // 0,4,8,12
            float4 a = *(const float4*)(x + (size_t)(m0 + r) * C_DIM + k0 + c);
            As[c + 0][r] = a.x;
            As[c + 1][r] = a.y;
            As[c + 2][r] = a.z;
            As[c + 3][r] = a.w;
        }
        // Load B tile 16x64 (256 float4, 1 per thread)
        {
            int r = tid >> 4;             // 0..15 (k)
            int c = (tid & 15) << 2;      // 0..60 (n)
            float4 bvec = *(const float4*)(W + (size_t)(k0 + r) * BN + c);
            *(float4*)&Bs[r][c] = bvec;
        }
        __syncthreads();

        #pragma unroll
        for (int k = 0; k < BK; k++) {
            float4 b4 = *(const float4*)&Bs[k][tx << 2];
            float4 a0 = *(const float4*)&As[k][ty << 3];
            float4 a1 = *(const float4*)&As[k][(ty << 3) + 4];
            float av[8] = {a0.x, a0.y, a0.z, a0.w, a1.x, a1.y, a1.z, a1.w};
            float bv[4] = {b4.x, b4.y, b4.z, b4.w};
            #pragma unroll
            for (int i = 0; i < 8; i++)
                #pragma unroll
                for (int j = 0; j < 4; j++)
                    acc[i][j] = fmaf(av[i], bv[j], acc[i][j]);
        }
        __syncthreads();
    }

    float* outp = g_qkv + (size_t)plane * M_TOTAL * H_DIM;
    #pragma unroll
    for (int i = 0; i < 8; i++) {
        int row = m0 + (ty << 3) + i;
        float4 v = make_float4(acc[i][0], acc[i][1], acc[i][2], acc[i][3]);
        *(float4*)(outp + (size_t)row * H_DIM + (tx << 2)) = v;
    }
}

// ---------------------------------------------------------------------------
// Kernel B: causal attention per batch.
// One CTA per batch (512 CTAs, 256 threads = 8 warps).
// smem: Q/K/V tiles [128][68] + per-warp weight rows [8][128].
// Each warp owns rows t = warp, warp+8, ...; lanes hold 4 score columns.
// ---------------------------------------------------------------------------
__global__ __launch_bounds__(256) void attn_kernel(float* __restrict__ out)
{
    extern __shared__ float sm[];
    float* Qs = sm;
    float* Ks = Qs + T_DIM * SROW;
    float* Vs = Ks + T_DIM * SROW;
    float* Wb = Vs + T_DIM * SROW;   // [8][128]

    const int b = blockIdx.x;
    const float* __restrict__ qg = g_qkv + (size_t)b * T_DIM * H_DIM;
    const float* __restrict__ kg = qg + (size_t)M_TOTAL * H_DIM;
    const float* __restrict__ vg = kg + (size_t)M_TOTAL * H_DIM;
    const int tid = threadIdx.x;

    // Stage Q, K, V into padded smem (float4 loads/stores; SROW%4==0 keeps alignment)
    for (int idx = tid; idx < (T_DIM * H_DIM) / 4; idx += 256) {
        int r = idx >> 4;
        int c = (idx & 15) << 2;
        *(float4*)(Qs + r * SROW + c) = *(const float4*)(qg + (size_t)r * H_DIM + c);
        *(float4*)(Ks + r * SROW + c) = *(const float4*)(kg + (size_t)r * H_DIM + c);
        *(float4*)(Vs + r * SROW + c) = *(const float4*)(vg + (size_t)r * H_DIM + c);
    }
    __syncthreads();

    const int warp = tid >> 5;
    const int lane = tid & 31;
    const float scale = 0.40824829046386301636f;   // 6^-0.5 (head_count scaling)

    for (int t = warp; t < T_DIM; t += 8) {
        const float* qrow = Qs + t * SROW;
        const float* kp0  = Ks + lane * SROW;

        // ---- scores: sc[j] = q[t] . k[lane + 32j] ----
        float sc[4] = {0.f, 0.f, 0.f, 0.f};
        #pragma unroll
        for (int h4 = 0; h4 < 16; h4++) {
            float4 qv = *(const float4*)(qrow + (h4 << 2));
            #pragma unroll
            for (int j = 0; j < 4; j++) {
                float4 kv = *(const float4*)(kp0 + j * 32 * SROW + (h4 << 2));
                sc[j] = fmaf(qv.x, kv.x, sc[j]);
                sc[j] = fmaf(qv.y, kv.y, sc[j]);
                sc[j] = fmaf(qv.z, kv.z, sc[j]);
                sc[j] = fmaf(qv.w, kv.w, sc[j]);
            }
        }
        #pragma unroll
        for (int j = 0; j < 4; j++) {
            int s = lane + (j << 5);
            sc[j] = (s <= t) ? sc[j] * scale : -1e30f;
        }

        // ---- softmax over the row (warp-wide) ----
        float mx = fmaxf(fmaxf(sc[0], sc[1]), fmaxf(sc[2], sc[3]));
        #pragma unroll
        for (int off = 16; off; off >>= 1)
            mx = fmaxf(mx, __shfl_xor_sync(0xffffffffu, mx, off));
        float e[4], ssum = 0.f;
        #pragma unroll
        for (int j = 0; j < 4; j++) { e[j] = __expf(sc[j] - mx); ssum += e[j]; }
        #pragma unroll
        for (int off = 16; off; off >>= 1)
            ssum += __shfl_xor_sync(0xffffffffu, ssum, off);
        float inv = __frcp_rn(ssum);

        float* wrow = Wb + (warp << 7);
        #pragma unroll
        for (int j = 0; j < 4; j++) wrow[lane + (j << 5)] = e[j] * inv;
        __syncwarp();

        // ---- out[t] = sum_{s<=t} w[s] * V[s] (lanes span h; 2 h each) ----
        float o0 = 0.f, o1 = 0.f;
        const float* vp = Vs + lane;
        for (int s = 0; s <= t; s++) {
            float w = wrow[s];
            o0 = fmaf(w, vp[s * SROW], o0);
            o1 = fmaf(w, vp[s * SROW + 32], o1);
        }
        float* op = out + (size_t)b * T_DIM * H_DIM + (size_t)t * H_DIM;
        op[lane]      = o0;
        op[lane + 32] = o1;
        __syncwarp();   // wrow write-after-read safety across t iterations
    }
}

// ---------------------------------------------------------------------------
extern "C" void kernel_launch(void* const* d_in, const int* in_sizes, int n_in,
                              void* d_out, int out_size)
{
    const float* x  = (const float*)d_in[0];
    const float* Wq = (const float*)d_in[1];
    const float* Wk = (const float*)d_in[2];
    const float* Wv = (const float*)d_in[3];
    float* out = (float*)d_out;

    dim3 g1(M_TOTAL / 128, 3);
    qkv_gemm_kernel<<<g1, 256>>>(x, Wq, Wk, Wv);

    int smem = (3 * T_DIM * SROW + 8 * T_DIM) * (int)sizeof(float);   // 108544 B
    cudaFuncSetAttribute(attn_kernel, cudaFuncAttributeMaxDynamicSharedMemorySize, smem);
    attn_kernel<<<B_DIM, 256, smem>>>(out);
}

// round 4
// speedup vs baseline: 1.4892x; 1.4892x over previous
#include <cuda_runtime.h>
#include <cuda_bf16.h>

#define M_TOTAL 65536   // B*T = 512*128
#define C_DIM   384
#define H_DIM   64
#define T_DIM   128
#define B_DIM   512
#define SROW    68      // attn smem row stride (floats)
#define ASTRIDE 40      // gemm smem row stride (bf16): conflict-free for frag loads

// Q,K,V planes: 3 * 65536 * 64 fp32 = 50.3 MB
__device__ float g_qkv[3u * M_TOTAL * H_DIM];
// Pre-transposed, bf16 hi/lo split weights: [n=192][k=384]
__device__ __nv_bfloat16 g_wh[192 * C_DIM];
__device__ __nv_bfloat16 g_wl[192 * C_DIM];

// ---------------------------------------------------------------------------
// Kernel 0: convert W -> transposed bf16 hi/lo. n = plane*64 + h.
// ---------------------------------------------------------------------------
__global__ __launch_bounds__(256) void wconv_kernel(
    const float* __restrict__ Wq, const float* __restrict__ Wk,
    const float* __restrict__ Wv)
{
    int idx = blockIdx.x * 256 + threadIdx.x;   // grid covers 192*384
    if (idx >= 192 * C_DIM) return;
    int n = idx / C_DIM;
    int k = idx % C_DIM;
    int plane = n >> 6;
    int h = n & 63;
    const float* W = (plane == 0) ? Wq : (plane == 1) ? Wk : Wv;
    float v = W[k * H_DIM + h];
    __nv_bfloat16 hi = __float2bfloat16_rn(v);
    __nv_bfloat16 lo = __float2bfloat16_rn(v - __bfloat162float(hi));
    g_wh[n * C_DIM + k] = hi;
    g_wl[n * C_DIM + k] = lo;
}

// ---------------------------------------------------------------------------
// bf16 mma.sync m16n8k16 (row.col), fp32 accumulate
// ---------------------------------------------------------------------------
__device__ __forceinline__ void mma16816(float* c, const unsigned* a,
                                         unsigned b0, unsigned b1)
{
    asm volatile(
        "mma.sync.aligned.m16n8k16.row.col.f32.bf16.bf16.f32 "
        "{%0,%1,%2,%3}, {%4,%5,%6,%7}, {%8,%9}, {%0,%1,%2,%3};"
        : "+f"(c[0]), "+f"(c[1]), "+f"(c[2]), "+f"(c[3])
        : "r"(a[0]), "r"(a[1]), "r"(a[2]), "r"(a[3]), "r"(b0), "r"(b1));
}

// ---------------------------------------------------------------------------
// Kernel A: fused QKV projection via split-bf16 tensor-core MMA.
// C[65536, 192] = x[65536, 384] @ Wt^T  (cols 0-63=Q, 64-127=K, 128-191=V)
// Tile BM=128, BN=192, BK=32; 256 threads = 8 warps as 4(m) x 2(n).
// x converted to bf16 hi/lo on the fly; 3 MMA combos (hh, hl, lh): err ~2^-16.
// ---------------------------------------------------------------------------
__global__ __launch_bounds__(256) void qkv_gemm_mma(const float* __restrict__ x)
{
    extern __shared__ __nv_bfloat16 smb[];
    __nv_bfloat16* Ah = smb;                 // 128*40
    __nv_bfloat16* Al = Ah + 128 * ASTRIDE;
    __nv_bfloat16* Bh = Al + 128 * ASTRIDE;  // 192*40
    __nv_bfloat16* Bl = Bh + 192 * ASTRIDE;

    const int tid  = threadIdx.x;
    const int warp = tid >> 5, lane = tid & 31;
    const int g = lane >> 2, ctg = lane & 3;
    const int wm = (warp & 3) * 32;    // 4 warps along m, 32 rows each
    const int wn = (warp >> 2) * 96;   // 2 warps along n, 96 cols each
    const int m0 = blockIdx.x * 128;

    float acc[2][12][4];
    #pragma unroll
    for (int a = 0; a < 2; a++)
        #pragma unroll
        for (int b = 0; b < 12; b++)
            #pragma unroll
            for (int c = 0; c < 4; c++) acc[a][b][c] = 0.f;

    float4 aPf[4];
    uint4  bPf[6];

    // prefetch k0 = 0
    #pragma unroll
    for (int i = 0; i < 4; i++) {
        int v = tid + (i << 8);
        int m = v >> 3, kq = (v & 7) << 2;
        aPf[i] = *(const float4*)(x + (size_t)(m0 + m) * C_DIM + kq);
    }
    #pragma unroll
    for (int i = 0; i < 6; i++) {
        int v = tid + (i << 8);
        int buf = (v >= 768);
        int vv = v - buf * 768;
        int n = vv >> 2, kq8 = (vv & 3) << 3;
        const __nv_bfloat16* src = (buf ? g_wl : g_wh) + n * C_DIM + kq8;
        bPf[i] = *(const uint4*)src;
    }

    for (int it = 0; it < C_DIM / 32; it++) {
        // ---- store prefetched tiles to smem (A converted to hi/lo) ----
        #pragma unroll
        for (int i = 0; i < 4; i++) {
            int v = tid + (i << 8);
            int m = v >> 3, kq = (v & 7) << 2;
            float4 a = aPf[i];
            __nv_bfloat16 hx = __float2bfloat16_rn(a.x);
            __nv_bfloat16 hy = __float2bfloat16_rn(a.y);
            __nv_bfloat16 hz = __float2bfloat16_rn(a.z);
            __nv_bfloat16 hw = __float2bfloat16_rn(a.w);
            __nv_bfloat16 lx = __float2bfloat16_rn(a.x - __bfloat162float(hx));
            __nv_bfloat16 ly = __float2bfloat16_rn(a.y - __bfloat162float(hy));
            __nv_bfloat16 lz = __float2bfloat16_rn(a.z - __bfloat162float(hz));
            __nv_bfloat16 lw = __float2bfloat16_rn(a.w - __bfloat162float(hw));
            __nv_bfloat162 p;
            p.x = hx; p.y = hy; *(__nv_bfloat162*)&Ah[m * ASTRIDE + kq] = p;
            p.x = hz; p.y = hw; *(__nv_bfloat162*)&Ah[m * ASTRIDE + kq + 2] = p;
            p.x = lx; p.y = ly; *(__nv_bfloat162*)&Al[m * ASTRIDE + kq] = p;
            p.x = lz; p.y = lw; *(__nv_bfloat162*)&Al[m * ASTRIDE + kq + 2] = p;
        }
        #pragma unroll
        for (int i = 0; i < 6; i++) {
            int v = tid + (i << 8);
            int buf = (v >= 768);
            int vv = v - buf * 768;
            int n = vv >> 2, kq8 = (vv & 3) << 3;
            *(uint4*)&(buf ? Bl : Bh)[n * ASTRIDE + kq8] = bPf[i];
        }
        __syncthreads();

        // ---- prefetch next k-chunk ----
        if (it + 1 < C_DIM / 32) {
            int k0n = (it + 1) * 32;
            #pragma unroll
            for (int i = 0; i < 4; i++) {
                int v = tid + (i << 8);
                int m = v >> 3, kq = (v & 7) << 2;
                aPf[i] = *(const float4*)(x + (size_t)(m0 + m) * C_DIM + k0n + kq);
            }
            #pragma unroll
            for (int i = 0; i < 6; i++) {
                int v = tid + (i << 8);
                int buf = (v >= 768);
                int vv = v - buf * 768;
                int n = vv >> 2, kq8 = (vv & 3) << 3;
                const __nv_bfloat16* src = (buf ? g_wl : g_wh) + n * C_DIM + k0n + kq8;
                bPf[i] = *(const uint4*)src;
            }
        }

        // ---- compute: 2 k16 steps ----
        #pragma unroll
        for (int ks = 0; ks < 2; ks++) {
            const int kb = ks * 16;
            unsigned ah[2][4], al[2][4];
            #pragma unroll
            for (int mt = 0; mt < 2; mt++) {
                int r = wm + mt * 16 + g;
                int c = kb + ctg * 2;
                ah[mt][0] = *(const unsigned*)&Ah[r * ASTRIDE + c];
                ah[mt][1] = *(const unsigned*)&Ah[(r + 8) * ASTRIDE + c];
                ah[mt][2] = *(const unsigned*)&Ah[r * ASTRIDE + c + 8];
                ah[mt][3] = *(const unsigned*)&Ah[(r + 8) * ASTRIDE + c + 8];
                al[mt][0] = *(const unsigned*)&Al[r * ASTRIDE + c];
                al[mt][1] = *(const unsigned*)&Al[(r + 8) * ASTRIDE + c];
                al[mt][2] = *(const unsigned*)&Al[r * ASTRIDE + c + 8];
                al[mt][3] = *(const unsigned*)&Al[(r + 8) * ASTRIDE + c + 8];
            }
            #pragma unroll
            for (int nt = 0; nt < 12; nt++) {
                int n = wn + nt * 8 + g;
                int c = kb + ctg * 2;
                unsigned bh0 = *(const unsigned*)&Bh[n * ASTRIDE + c];
                unsigned bh1 = *(const unsigned*)&Bh[n * ASTRIDE + c + 8];
                unsigned bl0 = *(const unsigned*)&Bl[n * ASTRIDE + c];
                unsigned bl1 = *(const unsigned*)&Bl[n * ASTRIDE + c + 8];
                #pragma unroll
                for (int mt = 0; mt < 2; mt++) {
                    mma16816(acc[mt][nt], ah[mt], bh0, bh1);
                    mma16816(acc[mt][nt], ah[mt], bl0, bl1);
                    mma16816(acc[mt][nt], al[mt], bh0, bh1);
                }
            }
        }
        __syncthreads();
    }

    // ---- epilogue: scatter into Q/K/V planes ----
    #pragma unroll
    for (int mt = 0; mt < 2; mt++)
        #pragma unroll
        for (int nt = 0; nt < 12; nt++) {
            int r = m0 + wm + mt * 16 + g;
            int n = wn + nt * 8 + ctg * 2;
            size_t base = (size_t)(n >> 6) * ((size_t)M_TOTAL * H_DIM) + (n & 63);
            *(float2*)&g_qkv[base + (size_t)r * H_DIM] =
                make_float2(acc[mt][nt][0], acc[mt][nt][1]);
            *(float2*)&g_qkv[base + (size_t)(r + 8) * H_DIM] =
                make_float2(acc[mt][nt][2], acc[mt][nt][3]);
        }
}

// ---------------------------------------------------------------------------
// Kernel B: causal attention, one CTA per batch, 8 warps.
// Each warp processes 4 rows per pass (shares K/V smem loads across rows);
// softmax weights kept in registers, broadcast via shuffle in AV.
// Masked weights are exactly 0 (exp underflow), so AV runs to the group max.
// ---------------------------------------------------------------------------
__global__ __launch_bounds__(256, 2) void attn_kernel(float* __restrict__ out)
{
    extern __shared__ float sm[];
    float* Qs = sm;
    float* Ks = Qs + T_DIM * SROW;
    float* Vs = Ks + T_DIM * SROW;

    const int b = blockIdx.x;
    const float* __restrict__ qg = g_qkv + (size_t)b * T_DIM * H_DIM;
    const float* __restrict__ kg = qg + (size_t)M_TOTAL * H_DIM;
    const float* __restrict__ vg = kg + (size_t)M_TOTAL * H_DIM;
    const int tid = threadIdx.x;

    for (int idx = tid; idx < (T_DIM * H_DIM) / 4; idx += 256) {
        int r = idx >> 4;
        int c = (idx & 15) << 2;
        *(float4*)(Qs + r * SROW + c) = *(const float4*)(qg + (size_t)r * H_DIM + c);
        *(float4*)(Ks + r * SROW + c) = *(const float4*)(kg + (size_t)r * H_DIM + c);
        *(float4*)(Vs + r * SROW + c) = *(const float4*)(vg + (size_t)r * H_DIM + c);
    }
    __syncthreads();

    const int warp = tid >> 5;
    const int lane = tid & 31;
    const float scale = 0.40824829046386301636f;   // 6^-0.5

    for (int p = 0; p < 4; p++) {
        const int tbase = warp + 32 * p;           // rows: tbase + 8*i, i<4

        // ---- scores for 4 rows, sharing K loads ----
        float sc[4][4];
        #pragma unroll
        for (int i = 0; i < 4; i++)
            #pragma unroll
            for (int j = 0; j < 4; j++) sc[i][j] = 0.f;

        #pragma unroll
        for (int h4 = 0; h4 < 16; h4++) {
            float4 kv[4];
            #pragma unroll
            for (int j = 0; j < 4; j++)
                kv[j] = *(const float4*)(Ks + (lane + (j << 5)) * SROW + (h4 << 2));
            #pragma unroll
            for (int i = 0; i < 4; i++) {
                float4 qv = *(const float4*)(Qs + (tbase + 8 * i) * SROW + (h4 << 2));
                #pragma unroll
                for (int j = 0; j < 4; j++) {
                    sc[i][j] = fmaf(qv.x, kv[j].x, sc[i][j]);
                    sc[i][j] = fmaf(qv.y, kv[j].y, sc[i][j]);
                    sc[i][j] = fmaf(qv.z, kv[j].z, sc[i][j]);
                    sc[i][j] = fmaf(qv.w, kv[j].w, sc[i][j]);
                }
            }
        }

        // ---- per-row causal softmax; weights live in registers ----
        float e[4][4];
        #pragma unroll
        for (int i = 0; i < 4; i++) {
            int t = tbase + 8 * i;
            #pragma unroll
            for (int j = 0; j < 4; j++) {
                int s = lane + (j << 5);
                sc[i][j] = (s <= t) ? sc[i][j] * scale : -1e30f;
            }
            float mx = fmaxf(fmaxf(sc[i][0], sc[i][1]), fmaxf(sc[i][2], sc[i][3]));
            #pragma unroll
            for (int off = 16; off; off >>= 1)
                mx = fmaxf(mx, __shfl_xor_sync(0xffffffffu, mx, off));
            float ssum = 0.f;
            #pragma unroll
            for (int j = 0; j < 4; j++) {
                e[i][j] = __expf(sc[i][j] - mx);   // exactly 0 for masked s
                ssum += e[i][j];
            }
            #pragma unroll
            for (int off = 16; off; off >>= 1)
                ssum += __shfl_xor_sync(0xffffffffu, ssum, off);
            float inv = __frcp_rn(ssum);
            #pragma unroll
            for (int j = 0; j < 4; j++) e[i][j] *= inv;
        }

        // ---- AV: share V loads across 4 rows; w via shuffle ----
        float o[4][2];
        #pragma unroll
        for (int i = 0; i < 4; i++) { o[i][0] = 0.f; o[i][1] = 0.f; }

        const int t3 = tbase + 24;                 // max row in group
        #pragma unroll
        for (int j = 0; j < 4; j++) {
            int s_end = (32 * j + 31 < t3) ? (32 * j + 31) : t3;
            for (int s = 32 * j; s <= s_end; s++) {
                float v0 = Vs[s * SROW + lane];
                float v1 = Vs[s * SROW + 32 + lane];
                int src = s & 31;
                #pragma unroll
                for (int i = 0; i < 4; i++) {
                    float w = __shfl_sync(0xffffffffu, e[i][j], src);
                    o[i][0] = fmaf(w, v0, o[i][0]);
                    o[i][1] = fmaf(w, v1, o[i][1]);
                }
            }
        }

        #pragma unroll
        for (int i = 0; i < 4; i++) {
            int t = tbase + 8 * i;
            float* op = out + (size_t)b * T_DIM * H_DIM + (size_t)t * H_DIM;
            op[lane]      = o[i][0];
            op[lane + 32] = o[i][1];
        }
    }
}

// ---------------------------------------------------------------------------
extern "C" void kernel_launch(void* const* d_in, const int* in_sizes, int n_in,
                              void* d_out, int out_size)
{
    const float* x  = (const float*)d_in[0];
    const float* Wq = (const float*)d_in[1];
    const float* Wk = (const float*)d_in[2];
    const float* Wv = (const float*)d_in[3];
    float* out = (float*)d_out;

    wconv_kernel<<<(192 * C_DIM + 255) / 256, 256>>>(Wq, Wk, Wv);

    int gsmem = (2 * 128 * ASTRIDE + 2 * 192 * ASTRIDE) * (int)sizeof(__nv_bfloat16); // 51200
    cudaFuncSetAttribute(qkv_gemm_mma, cudaFuncAttributeMaxDynamicSharedMemorySize, gsmem);
    qkv_gemm_mma<<<M_TOTAL / 128, 256, gsmem>>>(x);

    int asmem = 3 * T_DIM * SROW * (int)sizeof(float);   // 104448
    cudaFuncSetAttribute(attn_kernel, cudaFuncAttributeMaxDynamicSharedMemorySize, asmem);
    attn_kernel<<<B_DIM, 256, asmem>>>(out);
}

// round 5
// speedup vs baseline: 2.4210x; 1.6257x over previous
#include <cuda_runtime.h>
#include <cuda_bf16.h>

#define M_TOTAL 65536   // B*T = 512*128
#define C_DIM   384
#define H_DIM   64
#define T_DIM   128
#define B_DIM   512
#define ASTRIDE 40      // gemm smem row stride (bf16)
#define QSTR    72      // attn Q/K smem stride (bf16): conflict-free frag LDS
#define VSTR    136     // attn Vt smem stride (bf16)

// Q,K,V planes: 3 * 65536 * 64 fp32 = 50.3 MB
__device__ float g_qkv[3u * M_TOTAL * H_DIM];
// Pre-transposed, bf16 hi/lo split weights: [n=192][k=384]
__device__ __nv_bfloat16 g_wh[192 * C_DIM];
__device__ __nv_bfloat16 g_wl[192 * C_DIM];

// ---------------------------------------------------------------------------
// Kernel 0: convert W -> transposed bf16 hi/lo. n = plane*64 + h.
// ---------------------------------------------------------------------------
__global__ __launch_bounds__(256) void wconv_kernel(
    const float* __restrict__ Wq, const float* __restrict__ Wk,
    const float* __restrict__ Wv)
{
    int idx = blockIdx.x * 256 + threadIdx.x;
    if (idx >= 192 * C_DIM) return;
    int n = idx / C_DIM;
    int k = idx % C_DIM;
    int plane = n >> 6;
    int h = n & 63;
    const float* W = (plane == 0) ? Wq : (plane == 1) ? Wk : Wv;
    float v = W[k * H_DIM + h];
    __nv_bfloat16 hi = __float2bfloat16_rn(v);
    __nv_bfloat16 lo = __float2bfloat16_rn(v - __bfloat162float(hi));
    g_wh[n * C_DIM + k] = hi;
    g_wl[n * C_DIM + k] = lo;
}

// ---------------------------------------------------------------------------
// bf16 mma.sync m16n8k16 (row.col), fp32 accumulate
// ---------------------------------------------------------------------------
__device__ __forceinline__ void mma16816(float* c, const unsigned* a,
                                         unsigned b0, unsigned b1)
{
    asm volatile(
        "mma.sync.aligned.m16n8k16.row.col.f32.bf16.bf16.f32 "
        "{%0,%1,%2,%3}, {%4,%5,%6,%7}, {%8,%9}, {%0,%1,%2,%3};"
        : "+f"(c[0]), "+f"(c[1]), "+f"(c[2]), "+f"(c[3])
        : "r"(a[0]), "r"(a[1]), "r"(a[2]), "r"(a[3]), "r"(b0), "r"(b1));
}

// ---------------------------------------------------------------------------
// Kernel A: fused QKV projection via split-bf16 tensor-core MMA. (unchanged)
// ---------------------------------------------------------------------------
__global__ __launch_bounds__(256) void qkv_gemm_mma(const float* __restrict__ x)
{
    extern __shared__ __nv_bfloat16 smb[];
    __nv_bfloat16* Ah = smb;                 // 128*40
    __nv_bfloat16* Al = Ah + 128 * ASTRIDE;
    __nv_bfloat16* Bh = Al + 128 * ASTRIDE;  // 192*40
    __nv_bfloat16* Bl = Bh + 192 * ASTRIDE;

    const int tid  = threadIdx.x;
    const int warp = tid >> 5, lane = tid & 31;
    const int g = lane >> 2, ctg = lane & 3;
    const int wm = (warp & 3) * 32;
    const int wn = (warp >> 2) * 96;
    const int m0 = blockIdx.x * 128;

    float acc[2][12][4];
    #pragma unroll
    for (int a = 0; a < 2; a++)
        #pragma unroll
        for (int b = 0; b < 12; b++)
            #pragma unroll
            for (int c = 0; c < 4; c++) acc[a][b][c] = 0.f;

    float4 aPf[4];
    uint4  bPf[6];

    #pragma unroll
    for (int i = 0; i < 4; i++) {
        int v = tid + (i << 8);
        int m = v >> 3, kq = (v & 7) << 2;
        aPf[i] = *(const float4*)(x + (size_t)(m0 + m) * C_DIM + kq);
    }
    #pragma unroll
    for (int i = 0; i < 6; i++) {
        int v = tid + (i << 8);
        int buf = (v >= 768);
        int vv = v - buf * 768;
        int n = vv >> 2, kq8 = (vv & 3) << 3;
        const __nv_bfloat16* src = (buf ? g_wl : g_wh) + n * C_DIM + kq8;
        bPf[i] = *(const uint4*)src;
    }

    for (int it = 0; it < C_DIM / 32; it++) {
        #pragma unroll
        for (int i = 0; i < 4; i++) {
            int v = tid + (i << 8);
            int m = v >> 3, kq = (v & 7) << 2;
            float4 a = aPf[i];
            __nv_bfloat16 hx = __float2bfloat16_rn(a.x);
            __nv_bfloat16 hy = __float2bfloat16_rn(a.y);
            __nv_bfloat16 hz = __float2bfloat16_rn(a.z);
            __nv_bfloat16 hw = __float2bfloat16_rn(a.w);
            __nv_bfloat16 lx = __float2bfloat16_rn(a.x - __bfloat162float(hx));
            __nv_bfloat16 ly = __float2bfloat16_rn(a.y - __bfloat162float(hy));
            __nv_bfloat16 lz = __float2bfloat16_rn(a.z - __bfloat162float(hz));
            __nv_bfloat16 lw = __float2bfloat16_rn(a.w - __bfloat162float(hw));
            __nv_bfloat162 p;
            p.x = hx; p.y = hy; *(__nv_bfloat162*)&Ah[m * ASTRIDE + kq] = p;
            p.x = hz; p.y = hw; *(__nv_bfloat162*)&Ah[m * ASTRIDE + kq + 2] = p;
            p.x = lx; p.y = ly; *(__nv_bfloat162*)&Al[m * ASTRIDE + kq] = p;
            p.x = lz; p.y = lw; *(__nv_bfloat162*)&Al[m * ASTRIDE + kq + 2] = p;
        }
        #pragma unroll
        for (int i = 0; i < 6; i++) {
            int v = tid + (i << 8);
            int buf = (v >= 768);
            int vv = v - buf * 768;
            int n = vv >> 2, kq8 = (vv & 3) << 3;
            *(uint4*)&(buf ? Bl : Bh)[n * ASTRIDE + kq8] = bPf[i];
        }
        __syncthreads();

        if (it + 1 < C_DIM / 32) {
            int k0n = (it + 1) * 32;
            #pragma unroll
            for (int i = 0; i < 4; i++) {
                int v = tid + (i << 8);
                int m = v >> 3, kq = (v & 7) << 2;
                aPf[i] = *(const float4*)(x + (size_t)(m0 + m) * C_DIM + k0n + kq);
            }
            #pragma unroll
            for (int i = 0; i < 6; i++) {
                int v = tid + (i << 8);
                int buf = (v >= 768);
                int vv = v - buf * 768;
                int n = vv >> 2, kq8 = (vv & 3) << 3;
                const __nv_bfloat16* src = (buf ? g_wl : g_wh) + n * C_DIM + k0n + kq8;
                bPf[i] = *(const uint4*)src;
            }
        }

        #pragma unroll
        for (int ks = 0; ks < 2; ks++) {
            const int kb = ks * 16;
            unsigned ah[2][4], al[2][4];
            #pragma unroll
            for (int mt = 0; mt < 2; mt++) {
                int r = wm + mt * 16 + g;
                int c = kb + ctg * 2;
                ah[mt][0] = *(const unsigned*)&Ah[r * ASTRIDE + c];
                ah[mt][1] = *(const unsigned*)&Ah[(r + 8) * ASTRIDE + c];
                ah[mt][2] = *(const unsigned*)&Ah[r * ASTRIDE + c + 8];
                ah[mt][3] = *(const unsigned*)&Ah[(r + 8) * ASTRIDE + c + 8];
                al[mt][0] = *(const unsigned*)&Al[r * ASTRIDE + c];
                al[mt][1] = *(const unsigned*)&Al[(r + 8) * ASTRIDE + c];
                al[mt][2] = *(const unsigned*)&Al[r * ASTRIDE + c + 8];
                al[mt][3] = *(const unsigned*)&Al[(r + 8) * ASTRIDE + c + 8];
            }
            #pragma unroll
            for (int nt = 0; nt < 12; nt++) {
                int n = wn + nt * 8 + g;
                int c = kb + ctg * 2;
                unsigned bh0 = *(const unsigned*)&Bh[n * ASTRIDE + c];
                unsigned bh1 = *(const unsigned*)&Bh[n * ASTRIDE + c + 8];
                unsigned bl0 = *(const unsigned*)&Bl[n * ASTRIDE + c];
                unsigned bl1 = *(const unsigned*)&Bl[n * ASTRIDE + c + 8];
                #pragma unroll
                for (int mt = 0; mt < 2; mt++) {
                    mma16816(acc[mt][nt], ah[mt], bh0, bh1);
                    mma16816(acc[mt][nt], ah[mt], bl0, bl1);
                    mma16816(acc[mt][nt], al[mt], bh0, bh1);
                }
            }
        }
        __syncthreads();
    }

    #pragma unroll
    for (int mt = 0; mt < 2; mt++)
        #pragma unroll
        for (int nt = 0; nt < 12; nt++) {
            int r = m0 + wm + mt * 16 + g;
            int n = wn + nt * 8 + ctg * 2;
            size_t base = (size_t)(n >> 6) * ((size_t)M_TOTAL * H_DIM) + (n & 63);
            *(float2*)&g_qkv[base + (size_t)r * H_DIM] =
                make_float2(acc[mt][nt][0], acc[mt][nt][1]);
            *(float2*)&g_qkv[base + (size_t)(r + 8) * H_DIM] =
                make_float2(acc[mt][nt][2], acc[mt][nt][3]);
        }
}

// ---------------------------------------------------------------------------
// Kernel B: causal attention on tensor cores. One CTA per batch, 8 warps.
// Warp w owns rows [16w, 16w+16). S = Q K^T via split-bf16 (3 passes).
// Softmax on accumulator fragments; W repacked in-register into A fragments
// (m16n8 C layout == m16k16 A layout over 2 adjacent n-tiles); O = W V via
// split-bf16 with V transposed in smem. Causal tile skipping.
// ---------------------------------------------------------------------------
__global__ __launch_bounds__(256) void attn_mma(float* __restrict__ out)
{
    extern __shared__ __nv_bfloat16 smb[];
    __nv_bfloat16* Qh = smb;                  // [128][QSTR]
    __nv_bfloat16* Ql = Qh + 128 * QSTR;
    __nv_bfloat16* Kh = Ql + 128 * QSTR;
    __nv_bfloat16* Kl = Kh + 128 * QSTR;
    __nv_bfloat16* Vh = Kl + 128 * QSTR;      // transposed [64][VSTR]
    __nv_bfloat16* Vl = Vh + 64 * VSTR;

    const int b = blockIdx.x, tid = threadIdx.x;
    const float* __restrict__ qg = g_qkv + (size_t)b * T_DIM * H_DIM;
    const float* __restrict__ kg = qg + (size_t)M_TOTAL * H_DIM;
    const float* __restrict__ vg = kg + (size_t)M_TOTAL * H_DIM;

    // ---- stage + hi/lo split (V transposed) ----
    for (int idx = tid; idx < 2048; idx += 256) {
        int r = idx >> 4;           // token 0..127
        int c = (idx & 15) << 2;    // h 0,4,..,60
        float4 q = *(const float4*)(qg + (size_t)r * H_DIM + c);
        float4 k = *(const float4*)(kg + (size_t)r * H_DIM + c);
        float4 v = *(const float4*)(vg + (size_t)r * H_DIM + c);

        __nv_bfloat162 h2, l2;
        h2 = __floats2bfloat162_rn(q.x, q.y);
        l2 = __floats2bfloat162_rn(q.x - __low2float(h2), q.y - __high2float(h2));
        *(__nv_bfloat162*)&Qh[r * QSTR + c] = h2;
        *(__nv_bfloat162*)&Ql[r * QSTR + c] = l2;
        h2 = __floats2bfloat162_rn(q.z, q.w);
        l2 = __floats2bfloat162_rn(q.z - __low2float(h2), q.w - __high2float(h2));
        *(__nv_bfloat162*)&Qh[r * QSTR + c + 2] = h2;
        *(__nv_bfloat162*)&Ql[r * QSTR + c + 2] = l2;

        h2 = __floats2bfloat162_rn(k.x, k.y);
        l2 = __floats2bfloat162_rn(k.x - __low2float(h2), k.y - __high2float(h2));
        *(__nv_bfloat162*)&Kh[r * QSTR + c] = h2;
        *(__nv_bfloat162*)&Kl[r * QSTR + c] = l2;
        h2 = __floats2bfloat162_rn(k.z, k.w);
        l2 = __floats2bfloat162_rn(k.z - __low2float(h2), k.w - __high2float(h2));
        *(__nv_bfloat162*)&Kh[r * QSTR + c + 2] = h2;
        *(__nv_bfloat162*)&Kl[r * QSTR + c + 2] = l2;

        float vv[4] = {v.x, v.y, v.z, v.w};
        #pragma unroll
        for (int i = 0; i < 4; i++) {
            __nv_bfloat16 hi = __float2bfloat16_rn(vv[i]);
            __nv_bfloat16 lo = __float2bfloat16_rn(vv[i] - __bfloat162float(hi));
            Vh[(c + i) * VSTR + r] = hi;
            Vl[(c + i) * VSTR + r] = lo;
        }
    }
    __syncthreads();

    const int warp = tid >> 5, lane = tid & 31;
    const int g = lane >> 2, ctg = lane & 3;
    const int m0 = warp * 16;
    const int ntmax = 2 * warp + 1;        // last live score n-tile (inclusive)
    const float scale = 0.40824829046386301636f;   // 6^-0.5
    const float NEG = -1e30f;

    // ---- scores ----
    float S[16][4];
    #pragma unroll
    for (int nt = 0; nt < 16; nt++)
        #pragma unroll
        for (int j = 0; j < 4; j++) S[nt][j] = 0.f;

    #pragma unroll 1
    for (int kt = 0; kt < 4; kt++) {
        const int kc = kt * 16 + ctg * 2;
        unsigned ah[4], al[4];
        ah[0] = *(const unsigned*)&Qh[(m0 + g) * QSTR + kc];
        ah[1] = *(const unsigned*)&Qh[(m0 + 8 + g) * QSTR + kc];
        ah[2] = *(const unsigned*)&Qh[(m0 + g) * QSTR + kc + 8];
        ah[3] = *(const unsigned*)&Qh[(m0 + 8 + g) * QSTR + kc + 8];
        al[0] = *(const unsigned*)&Ql[(m0 + g) * QSTR + kc];
        al[1] = *(const unsigned*)&Ql[(m0 + 8 + g) * QSTR + kc];
        al[2] = *(const unsigned*)&Ql[(m0 + g) * QSTR + kc + 8];
        al[3] = *(const unsigned*)&Ql[(m0 + 8 + g) * QSTR + kc + 8];
        #pragma unroll
        for (int nt = 0; nt < 16; nt++) {
            if (nt <= ntmax) {
                unsigned bh0 = *(const unsigned*)&Kh[(nt * 8 + g) * QSTR + kc];
                unsigned bh1 = *(const unsigned*)&Kh[(nt * 8 + g) * QSTR + kc + 8];
                unsigned bl0 = *(const unsigned*)&Kl[(nt * 8 + g) * QSTR + kc];
                unsigned bl1 = *(const unsigned*)&Kl[(nt * 8 + g) * QSTR + kc + 8];
                mma16816(S[nt], ah, bh0, bh1);
                mma16816(S[nt], ah, bl0, bl1);
                mma16816(S[nt], al, bh0, bh1);
            }
        }
    }

    // ---- causal mask + softmax (rows t1 = m0+g with c0,c1; t2 = m0+8+g with c2,c3) ----
    const int t1 = m0 + g, t2 = m0 + 8 + g;
    float mx1 = NEG, mx2 = NEG;
    #pragma unroll
    for (int nt = 0; nt < 16; nt++) {
        if (nt <= ntmax) {
            int s0 = nt * 8 + ctg * 2;
            S[nt][0] = (s0     <= t1) ? S[nt][0] * scale : NEG;
            S[nt][1] = (s0 + 1 <= t1) ? S[nt][1] * scale : NEG;
            S[nt][2] = (s0     <= t2) ? S[nt][2] * scale : NEG;
            S[nt][3] = (s0 + 1 <= t2) ? S[nt][3] * scale : NEG;
            mx1 = fmaxf(mx1, fmaxf(S[nt][0], S[nt][1]));
            mx2 = fmaxf(mx2, fmaxf(S[nt][2], S[nt][3]));
        }
    }
    mx1 = fmaxf(mx1, __shfl_xor_sync(0xffffffffu, mx1, 1));
    mx1 = fmaxf(mx1, __shfl_xor_sync(0xffffffffu, mx1, 2));
    mx2 = fmaxf(mx2, __shfl_xor_sync(0xffffffffu, mx2, 1));
    mx2 = fmaxf(mx2, __shfl_xor_sync(0xffffffffu, mx2, 2));

    float sum1 = 0.f, sum2 = 0.f;
    #pragma unroll
    for (int nt = 0; nt < 16; nt++) {
        if (nt <= ntmax) {
            S[nt][0] = __expf(S[nt][0] - mx1);
            S[nt][1] = __expf(S[nt][1] - mx1);
            S[nt][2] = __expf(S[nt][2] - mx2);
            S[nt][3] = __expf(S[nt][3] - mx2);
            sum1 += S[nt][0] + S[nt][1];
            sum2 += S[nt][2] + S[nt][3];
        }
    }
    sum1 += __shfl_xor_sync(0xffffffffu, sum1, 1);
    sum1 += __shfl_xor_sync(0xffffffffu, sum1, 2);
    sum2 += __shfl_xor_sync(0xffffffffu, sum2, 1);
    sum2 += __shfl_xor_sync(0xffffffffu, sum2, 2);
    const float inv1 = __frcp_rn(sum1), inv2 = __frcp_rn(sum2);

    // ---- repack W into A fragments (hi/lo) ----
    unsigned wah[8][4], wal[8][4];
    #pragma unroll
    for (int kt2 = 0; kt2 < 8; kt2++) {
        if (kt2 <= warp) {
            float w0, w1;
            __nv_bfloat162 h2, l2;
            // reg0: row t1, tiles 2kt2 cols (c0,c1)
            w0 = S[2 * kt2][0] * inv1; w1 = S[2 * kt2][1] * inv1;
            h2 = __floats2bfloat162_rn(w0, w1);
            l2 = __floats2bfloat162_rn(w0 - __low2float(h2), w1 - __high2float(h2));
            wah[kt2][0] = *(unsigned*)&h2; wal[kt2][0] = *(unsigned*)&l2;
            // reg1: row t2, tile 2kt2 (c2,c3)
            w0 = S[2 * kt2][2] * inv2; w1 = S[2 * kt2][3] * inv2;
            h2 = __floats2bfloat162_rn(w0, w1);
            l2 = __floats2bfloat162_rn(w0 - __low2float(h2), w1 - __high2float(h2));
            wah[kt2][1] = *(unsigned*)&h2; wal[kt2][1] = *(unsigned*)&l2;
            // reg2: row t1, tile 2kt2+1 (c0,c1)
            w0 = S[2 * kt2 + 1][0] * inv1; w1 = S[2 * kt2 + 1][1] * inv1;
            h2 = __floats2bfloat162_rn(w0, w1);
            l2 = __floats2bfloat162_rn(w0 - __low2float(h2), w1 - __high2float(h2));
            wah[kt2][2] = *(unsigned*)&h2; wal[kt2][2] = *(unsigned*)&l2;
            // reg3: row t2, tile 2kt2+1 (c2,c3)
            w0 = S[2 * kt2 + 1][2] * inv2; w1 = S[2 * kt2 + 1][3] * inv2;
            h2 = __floats2bfloat162_rn(w0, w1);
            l2 = __floats2bfloat162_rn(w0 - __low2float(h2), w1 - __high2float(h2));
            wah[kt2][3] = *(unsigned*)&h2; wal[kt2][3] = *(unsigned*)&l2;
        }
    }

    // ---- O = W V ----
    float O[8][4];
    #pragma unroll
    for (int nt2 = 0; nt2 < 8; nt2++)
        #pragma unroll
        for (int j = 0; j < 4; j++) O[nt2][j] = 0.f;

    #pragma unroll
    for (int kt2 = 0; kt2 < 8; kt2++) {
        if (kt2 <= warp) {
            const int kc = kt2 * 16 + ctg * 2;
            #pragma unroll
            for (int nt2 = 0; nt2 < 8; nt2++) {
                unsigned bh0 = *(const unsigned*)&Vh[(nt2 * 8 + g) * VSTR + kc];
                unsigned bh1 = *(const unsigned*)&Vh[(nt2 * 8 + g) * VSTR + kc + 8];
                unsigned bl0 = *(const unsigned*)&Vl[(nt2 * 8 + g) * VSTR + kc];
                unsigned bl1 = *(const unsigned*)&Vl[(nt2 * 8 + g) * VSTR + kc + 8];
                mma16816(O[nt2], wah[kt2], bh0, bh1);
                mma16816(O[nt2], wah[kt2], bl0, bl1);
                mma16816(O[nt2], wal[kt2], bh0, bh1);
            }
        }
    }

    // ---- writeback ----
    float* ob = out + (size_t)b * T_DIM * H_DIM;
    #pragma unroll
    for (int nt2 = 0; nt2 < 8; nt2++) {
        int h0 = nt2 * 8 + ctg * 2;
        *(float2*)(ob + (size_t)t1 * H_DIM + h0) = make_float2(O[nt2][0], O[nt2][1]);
        *(float2*)(ob + (size_t)t2 * H_DIM + h0) = make_float2(O[nt2][2], O[nt2][3]);
    }
}

// ---------------------------------------------------------------------------
extern "C" void kernel_launch(void* const* d_in, const int* in_sizes, int n_in,
                              void* d_out, int out_size)
{
    const float* x  = (const float*)d_in[0];
    const float* Wq = (const float*)d_in[1];
    const float* Wk = (const float*)d_in[2];
    const float* Wv = (const float*)d_in[3];
    float* out = (float*)d_out;

    wconv_kernel<<<(192 * C_DIM + 255) / 256, 256>>>(Wq, Wk, Wv);

    int gsmem = (2 * 128 * ASTRIDE + 2 * 192 * ASTRIDE) * (int)sizeof(__nv_bfloat16); // 51200
    cudaFuncSetAttribute(qkv_gemm_mma, cudaFuncAttributeMaxDynamicSharedMemorySize, gsmem);
    qkv_gemm_mma<<<M_TOTAL / 128, 256, gsmem>>>(x);

    int asmem = (4 * 128 * QSTR + 2 * 64 * VSTR) * (int)sizeof(__nv_bfloat16);        // 108544
    cudaFuncSetAttribute(attn_mma, cudaFuncAttributeMaxDynamicSharedMemorySize, asmem);
    attn_mma<<<B_DIM, 256, asmem>>>(out);
}

// round 12
// speedup vs baseline: 2.5926x; 1.0708x over previous
#include <cuda_runtime.h>
#include <cuda_bf16.h>
#include <cstdint>

#define M_TOTAL 65536   // B*T = 512*128
#define C_DIM   384
#define H_DIM   64
#define T_DIM   128
#define B_DIM   512
#define ASTRIDE 40      // gemm smem row stride (bf16)
#define QSTR    72      // attn Q/K smem stride (bf16)
#define VSTR    136     // attn Vt smem stride (bf16)

// Pre-transposed, bf16 hi/lo split weights: [n=192][k=384]
__device__ __nv_bfloat16 g_wh[192 * C_DIM];
__device__ __nv_bfloat16 g_wl[192 * C_DIM];

// ---------------------------------------------------------------------------
// Kernel 0: convert W -> transposed bf16 hi/lo. n = plane*64 + h.
// ---------------------------------------------------------------------------
__global__ __launch_bounds__(256) void wconv_kernel(
    const float* __restrict__ Wq, const float* __restrict__ Wk,
    const float* __restrict__ Wv)
{
    int idx = blockIdx.x * 256 + threadIdx.x;
    if (idx >= 192 * C_DIM) return;
    int n = idx / C_DIM;
    int k = idx % C_DIM;
    int plane = n >> 6;
    int h = n & 63;
    const float* W = (plane == 0) ? Wq : (plane == 1) ? Wk : Wv;
    float v = W[k * H_DIM + h];
    __nv_bfloat16 hi = __float2bfloat16_rn(v);
    __nv_bfloat16 lo = __float2bfloat16_rn(v - __bfloat162float(hi));
    g_wh[n * C_DIM + k] = hi;
    g_wl[n * C_DIM + k] = lo;
}

// ---------------------------------------------------------------------------
// bf16 mma.sync m16n8k16 (row.col), fp32 accumulate
// ---------------------------------------------------------------------------
__device__ __forceinline__ void mma16816(float* c, const unsigned* a,
                                         unsigned b0, unsigned b1)
{
    asm volatile(
        "mma.sync.aligned.m16n8k16.row.col.f32.bf16.bf16.f32 "
        "{%0,%1,%2,%3}, {%4,%5,%6,%7}, {%8,%9}, {%0,%1,%2,%3};"
        : "+f"(c[0]), "+f"(c[1]), "+f"(c[2]), "+f"(c[3])
        : "r"(a[0]), "r"(a[1]), "r"(a[2]), "r"(a[3]), "r"(b0), "r"(b1));
}

// ===========================================================================
// Fused kernel: one CTA per batch (512 CTAs, 256 threads = 8 warps).
// Phase 1: QKV projection (split-bf16 HMMA, BM=128, BN=192, BK=32) with
//          accumulators written straight into the attention smem layouts.
// Phase 2: causal attention on HMMA (proven R4 structure), no gmem staging.
// ===========================================================================
__global__ __launch_bounds__(256) void fused_head(
    const float* __restrict__ x, float* __restrict__ out)
{
    extern __shared__ __nv_bfloat16 smb[];
    // phase-1 aliases
    __nv_bfloat16* Ah = smb;                 // 128*40
    __nv_bfloat16* Al = Ah + 128 * ASTRIDE;
    __nv_bfloat16* Bh = Al + 128 * ASTRIDE;  // 192*40
    __nv_bfloat16* Bl = Bh + 192 * ASTRIDE;
    // phase-2 aliases (same storage, larger footprint)
    __nv_bfloat16* Qh = smb;                 // [128][QSTR]
    __nv_bfloat16* Ql = Qh + 128 * QSTR;
    __nv_bfloat16* Kh = Ql + 128 * QSTR;
    __nv_bfloat16* Kl = Kh + 128 * QSTR;
    __nv_bfloat16* Vh = Kl + 128 * QSTR;     // transposed [64][VSTR]
    __nv_bfloat16* Vl = Vh + 64 * VSTR;

    const int tid  = threadIdx.x;
    const int warp = tid >> 5, lane = tid & 31;
    const int g = lane >> 2, ctg = lane & 3;
    const int b = blockIdx.x;
    const int m0 = b * 128;                  // row base in x (= batch b tokens)

    // ======================= Phase 1: QKV GEMM =======================
    const int wm = (warp & 3) * 32;          // 4 warps along m
    const int wn = (warp >> 2) * 96;         // 2 warps along n

    float acc[2][12][4];
    #pragma unroll
    for (int a = 0; a < 2; a++)
        #pragma unroll
        for (int bb = 0; bb < 12; bb++)
            #pragma unroll
            for (int c = 0; c < 4; c++) acc[a][bb][c] = 0.f;

    float4 aPf[4];
    uint4  bPf[6];

    #pragma unroll
    for (int i = 0; i < 4; i++) {
        int v = tid + (i << 8);
        int m = v >> 3, kq = (v & 7) << 2;
        aPf[i] = *(const float4*)(x + (size_t)(m0 + m) * C_DIM + kq);
    }
    #pragma unroll
    for (int i = 0; i < 6; i++) {
        int v = tid + (i << 8);
        int buf = (v >= 768);
        int vv = v - buf * 768;
        int n = vv >> 2, kq8 = (vv & 3) << 3;
        const __nv_bfloat16* src = (buf ? g_wl : g_wh) + n * C_DIM + kq8;
        bPf[i] = *(const uint4*)src;
    }

    for (int it = 0; it < C_DIM / 32; it++) {
        #pragma unroll
        for (int i = 0; i < 4; i++) {
            int v = tid + (i << 8);
            int m = v >> 3, kq = (v & 7) << 2;
            float4 a = aPf[i];
            __nv_bfloat16 hx = __float2bfloat16_rn(a.x);
            __nv_bfloat16 hy = __float2bfloat16_rn(a.y);
            __nv_bfloat16 hz = __float2bfloat16_rn(a.z);
            __nv_bfloat16 hw = __float2bfloat16_rn(a.w);
            __nv_bfloat16 lx = __float2bfloat16_rn(a.x - __bfloat162float(hx));
            __nv_bfloat16 ly = __float2bfloat16_rn(a.y - __bfloat162float(hy));
            __nv_bfloat16 lz = __float2bfloat16_rn(a.z - __bfloat162float(hz));
            __nv_bfloat16 lw = __float2bfloat16_rn(a.w - __bfloat162float(hw));
            __nv_bfloat162 p;
            p.x = hx; p.y = hy; *(__nv_bfloat162*)&Ah[m * ASTRIDE + kq] = p;
            p.x = hz; p.y = hw; *(__nv_bfloat162*)&Ah[m * ASTRIDE + kq + 2] = p;
            p.x = lx; p.y = ly; *(__nv_bfloat162*)&Al[m * ASTRIDE + kq] = p;
            p.x = lz; p.y = lw; *(__nv_bfloat162*)&Al[m * ASTRIDE + kq + 2] = p;
        }
        #pragma unroll
        for (int i = 0; i < 6; i++) {
            int v = tid + (i << 8);
            int buf = (v >= 768);
            int vv = v - buf * 768;
            int n = vv >> 2, kq8 = (vv & 3) << 3;
            *(uint4*)&(buf ? Bl : Bh)[n * ASTRIDE + kq8] = bPf[i];
        }
        __syncthreads();

        if (it + 1 < C_DIM / 32) {
            int k0n = (it + 1) * 32;
            #pragma unroll
            for (int i = 0; i < 4; i++) {
                int v = tid + (i << 8);
                int m = v >> 3, kq = (v & 7) << 2;
                aPf[i] = *(const float4*)(x + (size_t)(m0 + m) * C_DIM + k0n + kq);
            }
            #pragma unroll
            for (int i = 0; i < 6; i++) {
                int v = tid + (i << 8);
                int buf = (v >= 768);
                int vv = v - buf * 768;
                int n = vv >> 2, kq8 = (vv & 3) << 3;
                const __nv_bfloat16* src = (buf ? g_wl : g_wh) + n * C_DIM + k0n + kq8;
                bPf[i] = *(const uint4*)src;
            }
        }

        #pragma unroll
        for (int ks = 0; ks < 2; ks++) {
            const int kb = ks * 16;
            unsigned ah[2][4], al[2][4];
            #pragma unroll
            for (int mt = 0; mt < 2; mt++) {
                int r = wm + mt * 16 + g;
                int c = kb + ctg * 2;
                ah[mt][0] = *(const unsigned*)&Ah[r * ASTRIDE + c];
                ah[mt][1] = *(const unsigned*)&Ah[(r + 8) * ASTRIDE + c];
                ah[mt][2] = *(const unsigned*)&Ah[r * ASTRIDE + c + 8];
                ah[mt][3] = *(const unsigned*)&Ah[(r + 8) * ASTRIDE + c + 8];
                al[mt][0] = *(const unsigned*)&Al[r * ASTRIDE + c];
                al[mt][1] = *(const unsigned*)&Al[(r + 8) * ASTRIDE + c];
                al[mt][2] = *(const unsigned*)&Al[r * ASTRIDE + c + 8];
                al[mt][3] = *(const unsigned*)&Al[(r + 8) * ASTRIDE + c + 8];
            }
            #pragma unroll
            for (int nt = 0; nt < 12; nt++) {
                int n = wn + nt * 8 + g;
                int c = kb + ctg * 2;
                unsigned bh0 = *(const unsigned*)&Bh[n * ASTRIDE + c];
                unsigned bh1 = *(const unsigned*)&Bh[n * ASTRIDE + c + 8];
                unsigned bl0 = *(const unsigned*)&Bl[n * ASTRIDE + c];
                unsigned bl1 = *(const unsigned*)&Bl[n * ASTRIDE + c + 8];
                #pragma unroll
                for (int mt = 0; mt < 2; mt++) {
                    mma16816(acc[mt][nt], ah[mt], bh0, bh1);
                    mma16816(acc[mt][nt], ah[mt], bl0, bl1);
                    mma16816(acc[mt][nt], al[mt], bh0, bh1);
                }
            }
        }
        __syncthreads();
    }

    // ---- epilogue: split hi/lo and write DIRECTLY into attention layouts ----
    #pragma unroll
    for (int mt = 0; mt < 2; mt++)
        #pragma unroll
        for (int nt = 0; nt < 12; nt++) {
            int r0 = wm + mt * 16 + g;
            int r1 = r0 + 8;
            int n = wn + nt * 8 + ctg * 2;
            #pragma unroll
            for (int half = 0; half < 2; half++) {
                int r = half ? r1 : r0;
                float c0 = acc[mt][nt][half * 2 + 0];
                float c1 = acc[mt][nt][half * 2 + 1];
                __nv_bfloat162 h2 = __floats2bfloat162_rn(c0, c1);
                __nv_bfloat162 l2 = __floats2bfloat162_rn(c0 - __low2float(h2),
                                                          c1 - __high2float(h2));
                if (n < 64) {
                    *(__nv_bfloat162*)&Qh[r * QSTR + n] = h2;
                    *(__nv_bfloat162*)&Ql[r * QSTR + n] = l2;
                } else if (n < 128) {
                    *(__nv_bfloat162*)&Kh[r * QSTR + (n - 64)] = h2;
                    *(__nv_bfloat162*)&Kl[r * QSTR + (n - 64)] = l2;
                } else {
                    int h = n - 128;
                    Vh[h * VSTR + r]       = h2.x;
                    Vh[(h + 1) * VSTR + r] = h2.y;
                    Vl[h * VSTR + r]       = l2.x;
                    Vl[(h + 1) * VSTR + r] = l2.y;
                }
            }
        }
    __syncthreads();

    // ======================= Phase 2: attention =======================
    const int am0 = warp * 16;
    const int ntmax = 2 * warp + 1;
    const float scale = 0.40824829046386301636f;   // 6^-0.5
    const float NEG = -1e30f;

    float S[16][4];
    #pragma unroll
    for (int nt = 0; nt < 16; nt++)
        #pragma unroll
        for (int j = 0; j < 4; j++) S[nt][j] = 0.f;

    #pragma unroll 1
    for (int kt = 0; kt < 4; kt++) {
        const int kc = kt * 16 + ctg * 2;
        unsigned ah[4], al[4];
        ah[0] = *(const unsigned*)&Qh[(am0 + g) * QSTR + kc];
        ah[1] = *(const unsigned*)&Qh[(am0 + 8 + g) * QSTR + kc];
        ah[2] = *(const unsigned*)&Qh[(am0 + g) * QSTR + kc + 8];
        ah[3] = *(const unsigned*)&Qh[(am0 + 8 + g) * QSTR + kc + 8];
        al[0] = *(const unsigned*)&Ql[(am0 + g) * QSTR + kc];
        al[1] = *(const unsigned*)&Ql[(am0 + 8 + g) * QSTR + kc];
        al[2] = *(const unsigned*)&Ql[(am0 + g) * QSTR + kc + 8];
        al[3] = *(const unsigned*)&Ql[(am0 + 8 + g) * QSTR + kc + 8];
        #pragma unroll
        for (int nt = 0; nt < 16; nt++) {
            if (nt <= ntmax) {
                unsigned bh0 = *(const unsigned*)&Kh[(nt * 8 + g) * QSTR + kc];
                unsigned bh1 = *(const unsigned*)&Kh[(nt * 8 + g) * QSTR + kc + 8];
                unsigned bl0 = *(const unsigned*)&Kl[(nt * 8 + g) * QSTR + kc];
                unsigned bl1 = *(const unsigned*)&Kl[(nt * 8 + g) * QSTR + kc + 8];
                mma16816(S[nt], ah, bh0, bh1);
                mma16816(S[nt], ah, bl0, bl1);
                mma16816(S[nt], al, bh0, bh1);
            }
        }
    }

    const int t1 = am0 + g, t2 = am0 + 8 + g;
    float mx1 = NEG, mx2 = NEG;
    #pragma unroll
    for (int nt = 0; nt < 16; nt++) {
        if (nt <= ntmax) {
            int s0 = nt * 8 + ctg * 2;
            S[nt][0] = (s0     <= t1) ? S[nt][0] * scale : NEG;
            S[nt][1] = (s0 + 1 <= t1) ? S[nt][1] * scale : NEG;
            S[nt][2] = (s0     <= t2) ? S[nt][2] * scale : NEG;
            S[nt][3] = (s0 + 1 <= t2) ? S[nt][3] * scale : NEG;
            mx1 = fmaxf(mx1, fmaxf(S[nt][0], S[nt][1]));
            mx2 = fmaxf(mx2, fmaxf(S[nt][2], S[nt][3]));
        }
    }
    mx1 = fmaxf(mx1, __shfl_xor_sync(0xffffffffu, mx1, 1));
    mx1 = fmaxf(mx1, __shfl_xor_sync(0xffffffffu, mx1, 2));
    mx2 = fmaxf(mx2, __shfl_xor_sync(0xffffffffu, mx2, 1));
    mx2 = fmaxf(mx2, __shfl_xor_sync(0xffffffffu, mx2, 2));

    float sum1 = 0.f, sum2 = 0.f;
    #pragma unroll
    for (int nt = 0; nt < 16; nt++) {
        if (nt <= ntmax) {
            S[nt][0] = __expf(S[nt][0] - mx1);
            S[nt][1] = __expf(S[nt][1] - mx1);
            S[nt][2] = __expf(S[nt][2] - mx2);
            S[nt][3] = __expf(S[nt][3] - mx2);
            sum1 += S[nt][0] + S[nt][1];
            sum2 += S[nt][2] + S[nt][3];
        }
    }
    sum1 += __shfl_xor_sync(0xffffffffu, sum1, 1);
    sum1 += __shfl_xor_sync(0xffffffffu, sum1, 2);
    sum2 += __shfl_xor_sync(0xffffffffu, sum2, 1);
    sum2 += __shfl_xor_sync(0xffffffffu, sum2, 2);
    const float inv1 = __frcp_rn(sum1), inv2 = __frcp_rn(sum2);

    unsigned wah[8][4], wal[8][4];
    #pragma unroll
    for (int kt2 = 0; kt2 < 8; kt2++) {
        if (kt2 <= warp) {
            float w0, w1;
            __nv_bfloat162 h2, l2;
            w0 = S[2 * kt2][0] * inv1; w1 = S[2 * kt2][1] * inv1;
            h2 = __floats2bfloat162_rn(w0, w1);
            l2 = __floats2bfloat162_rn(w0 - __low2float(h2), w1 - __high2float(h2));
            wah[kt2][0] = *(unsigned*)&h2; wal[kt2][0] = *(unsigned*)&l2;
            w0 = S[2 * kt2][2] * inv2; w1 = S[2 * kt2][3] * inv2;
            h2 = __floats2bfloat162_rn(w0, w1);
            l2 = __floats2bfloat162_rn(w0 - __low2float(h2), w1 - __high2float(h2));
            wah[kt2][1] = *(unsigned*)&h2; wal[kt2][1] = *(unsigned*)&l2;
            w0 = S[2 * kt2 + 1][0] * inv1; w1 = S[2 * kt2 + 1][1] * inv1;
            h2 = __floats2bfloat162_rn(w0, w1);
            l2 = __floats2bfloat162_rn(w0 - __low2float(h2), w1 - __high2float(h2));
            wah[kt2][2] = *(unsigned*)&h2; wal[kt2][2] = *(unsigned*)&l2;
            w0 = S[2 * kt2 + 1][2] * inv2; w1 = S[2 * kt2 + 1][3] * inv2;
            h2 = __floats2bfloat162_rn(w0, w1);
            l2 = __floats2bfloat162_rn(w0 - __low2float(h2), w1 - __high2float(h2));
            wah[kt2][3] = *(unsigned*)&h2; wal[kt2][3] = *(unsigned*)&l2;
        }
    }

    float O[8][4];
    #pragma unroll
    for (int nt2 = 0; nt2 < 8; nt2++)
        #pragma unroll
        for (int j = 0; j < 4; j++) O[nt2][j] = 0.f;

    #pragma unroll
    for (int kt2 = 0; kt2 < 8; kt2++) {
        if (kt2 <= warp) {
            const int kc = kt2 * 16 + ctg * 2;
            #pragma unroll
            for (int nt2 = 0; nt2 < 8; nt2++) {
                unsigned bh0 = *(const unsigned*)&Vh[(nt2 * 8 + g) * VSTR + kc];
                unsigned bh1 = *(const unsigned*)&Vh[(nt2 * 8 + g) * VSTR + kc + 8];
                unsigned bl0 = *(const unsigned*)&Vl[(nt2 * 8 + g) * VSTR + kc];
                unsigned bl1 = *(const unsigned*)&Vl[(nt2 * 8 + g) * VSTR + kc + 8];
                mma16816(O[nt2], wah[kt2], bh0, bh1);
                mma16816(O[nt2], wah[kt2], bl0, bl1);
                mma16816(O[nt2], wal[kt2], bh0, bh1);
            }
        }
    }

    float* ob = out + (size_t)b * T_DIM * H_DIM;
    #pragma unroll
    for (int nt2 = 0; nt2 < 8; nt2++) {
        int h0 = nt2 * 8 + ctg * 2;
        *(float2*)(ob + (size_t)t1 * H_DIM + h0) = make_float2(O[nt2][0], O[nt2][1]);
        *(float2*)(ob + (size_t)t2 * H_DIM + h0) = make_float2(O[nt2][2], O[nt2][3]);
    }
}

// ---------------------------------------------------------------------------
extern "C" void kernel_launch(void* const* d_in, const int* in_sizes, int n_in,
                              void* d_out, int out_size)
{
    const float* x  = (const float*)d_in[0];
    const float* Wq = (const float*)d_in[1];
    const float* Wk = (const float*)d_in[2];
    const float* Wv = (const float*)d_in[3];
    float* out = (float*)d_out;

    wconv_kernel<<<(192 * C_DIM + 255) / 256, 256>>>(Wq, Wk, Wv);

    int fsmem = (4 * 128 * QSTR + 2 * 64 * VSTR) * (int)sizeof(__nv_bfloat16);  // 108544
    cudaFuncSetAttribute(fused_head, cudaFuncAttributeMaxDynamicSharedMemorySize, fsmem);
    fused_head<<<B_DIM, 256, fsmem>>>(x, out);
}

// round 13
// speedup vs baseline: 3.0318x; 1.1694x over previous
#include <cuda_runtime.h>
#include <cuda_bf16.h>
#include <cstdint>

#define M_TOTAL 65536   // B*T = 512*128
#define C_DIM   384
#define H_DIM   64
#define T_DIM   128
#define B_DIM   512
#define ASTRIDE 40      // gemm smem row stride (bf16)
#define QSTR    72      // attn Q/K smem stride (bf16)
#define VSTR    136     // attn Vt smem stride (bf16)

// Pre-transposed, bf16 hi/lo split weights: [n=192][k=384]
__device__ __nv_bfloat16 g_wh[192 * C_DIM];
__device__ __nv_bfloat16 g_wl[192 * C_DIM];

// ---------------------------------------------------------------------------
// Kernel 0: convert W -> transposed bf16 hi/lo. n = plane*64 + h.
// ---------------------------------------------------------------------------
__global__ __launch_bounds__(256) void wconv_kernel(
    const float* __restrict__ Wq, const float* __restrict__ Wk,
    const float* __restrict__ Wv)
{
    int idx = blockIdx.x * 256 + threadIdx.x;
    if (idx >= 192 * C_DIM) return;
    int n = idx / C_DIM;
    int k = idx % C_DIM;
    int plane = n >> 6;
    int h = n & 63;
    const float* W = (plane == 0) ? Wq : (plane == 1) ? Wk : Wv;
    float v = W[k * H_DIM + h];
    __nv_bfloat16 hi = __float2bfloat16_rn(v);
    __nv_bfloat16 lo = __float2bfloat16_rn(v - __bfloat162float(hi));
    g_wh[n * C_DIM + k] = hi;
    g_wl[n * C_DIM + k] = lo;
}

// ---------------------------------------------------------------------------
// bf16 mma.sync m16n8k16 (row.col), fp32 accumulate
// ---------------------------------------------------------------------------
__device__ __forceinline__ void mma16816(float* c, const unsigned* a,
                                         unsigned b0, unsigned b1)
{
    asm volatile(
        "mma.sync.aligned.m16n8k16.row.col.f32.bf16.bf16.f32 "
        "{%0,%1,%2,%3}, {%4,%5,%6,%7}, {%8,%9}, {%0,%1,%2,%3};"
        : "+f"(c[0]), "+f"(c[1]), "+f"(c[2]), "+f"(c[3])
        : "r"(a[0]), "r"(a[1]), "r"(a[2]), "r"(a[3]), "r"(b0), "r"(b1));
}

// ===========================================================================
// Fused kernel: one CTA per batch (512 CTAs, 256 threads = 8 warps).
// __launch_bounds__(256, 2): cap regs at 128 so 2 CTAs co-reside per SM
// (smem 2x108.5KB = 217KB fits the 228KB carveout) to hide MMA/mem latency.
// Phase 1: QKV projection (split-bf16 HMMA), accumulators written straight
//          into the attention smem layouts. No prefetch regs (occ hides it).
// Phase 2: causal attention on HMMA; W fragments converted on the fly.
// ===========================================================================
__global__ __launch_bounds__(256, 2) void fused_head(
    const float* __restrict__ x, float* __restrict__ out)
{
    extern __shared__ __nv_bfloat16 smb[];
    // phase-1 aliases
    __nv_bfloat16* Ah = smb;                 // 128*40
    __nv_bfloat16* Al = Ah + 128 * ASTRIDE;
    __nv_bfloat16* Bh = Al + 128 * ASTRIDE;  // 192*40
    __nv_bfloat16* Bl = Bh + 192 * ASTRIDE;
    // phase-2 aliases (same storage, larger footprint)
    __nv_bfloat16* Qh = smb;                 // [128][QSTR]
    __nv_bfloat16* Ql = Qh + 128 * QSTR;
    __nv_bfloat16* Kh = Ql + 128 * QSTR;
    __nv_bfloat16* Kl = Kh + 128 * QSTR;
    __nv_bfloat16* Vh = Kl + 128 * QSTR;     // transposed [64][VSTR]
    __nv_bfloat16* Vl = Vh + 64 * VSTR;

    const int tid  = threadIdx.x;
    const int warp = tid >> 5, lane = tid & 31;
    const int g = lane >> 2, ctg = lane & 3;
    const int b = blockIdx.x;
    const int m0 = b * 128;

    // ======================= Phase 1: QKV GEMM =======================
    const int wm = (warp & 3) * 32;          // 4 warps along m
    const int wn = (warp >> 2) * 96;         // 2 warps along n

    float acc[2][12][4];
    #pragma unroll
    for (int a = 0; a < 2; a++)
        #pragma unroll
        for (int bb = 0; bb < 12; bb++)
            #pragma unroll
            for (int c = 0; c < 4; c++) acc[a][bb][c] = 0.f;

    for (int it = 0; it < C_DIM / 32; it++) {
        const int k0 = it * 32;
        // A tile: load fp32, split hi/lo, store smem
        #pragma unroll
        for (int i = 0; i < 4; i++) {
            int v = tid + (i << 8);
            int m = v >> 3, kq = (v & 7) << 2;
            float4 a = *(const float4*)(x + (size_t)(m0 + m) * C_DIM + k0 + kq);
            __nv_bfloat162 h0 = __floats2bfloat162_rn(a.x, a.y);
            __nv_bfloat162 h1 = __floats2bfloat162_rn(a.z, a.w);
            __nv_bfloat162 l0 = __floats2bfloat162_rn(a.x - __low2float(h0),
                                                      a.y - __high2float(h0));
            __nv_bfloat162 l1 = __floats2bfloat162_rn(a.z - __low2float(h1),
                                                      a.w - __high2float(h1));
            *(__nv_bfloat162*)&Ah[m * ASTRIDE + kq]     = h0;
            *(__nv_bfloat162*)&Ah[m * ASTRIDE + kq + 2] = h1;
            *(__nv_bfloat162*)&Al[m * ASTRIDE + kq]     = l0;
            *(__nv_bfloat162*)&Al[m * ASTRIDE + kq + 2] = l1;
        }
        // B tiles (pre-split in gmem)
        #pragma unroll
        for (int i = 0; i < 6; i++) {
            int v = tid + (i << 8);
            int buf = (v >= 768);
            int vv = v - buf * 768;
            int n = vv >> 2, kq8 = (vv & 3) << 3;
            const __nv_bfloat16* src = (buf ? g_wl : g_wh) + n * C_DIM + k0 + kq8;
            *(uint4*)&(buf ? Bl : Bh)[n * ASTRIDE + kq8] = *(const uint4*)src;
        }
        __syncthreads();

        #pragma unroll
        for (int ks = 0; ks < 2; ks++) {
            const int kb = ks * 16;
            unsigned ah[2][4], al[2][4];
            #pragma unroll
            for (int mt = 0; mt < 2; mt++) {
                int r = wm + mt * 16 + g;
                int c = kb + ctg * 2;
                ah[mt][0] = *(const unsigned*)&Ah[r * ASTRIDE + c];
                ah[mt][1] = *(const unsigned*)&Ah[(r + 8) * ASTRIDE + c];
                ah[mt][2] = *(const unsigned*)&Ah[r * ASTRIDE + c + 8];
                ah[mt][3] = *(const unsigned*)&Ah[(r + 8) * ASTRIDE + c + 8];
                al[mt][0] = *(const unsigned*)&Al[r * ASTRIDE + c];
                al[mt][1] = *(const unsigned*)&Al[(r + 8) * ASTRIDE + c];
                al[mt][2] = *(const unsigned*)&Al[r * ASTRIDE + c + 8];
                al[mt][3] = *(const unsigned*)&Al[(r + 8) * ASTRIDE + c + 8];
            }
            #pragma unroll
            for (int nt = 0; nt < 12; nt++) {
                int n = wn + nt * 8 + g;
                int c = kb + ctg * 2;
                unsigned bh0 = *(const unsigned*)&Bh[n * ASTRIDE + c];
                unsigned bh1 = *(const unsigned*)&Bh[n * ASTRIDE + c + 8];
                unsigned bl0 = *(const unsigned*)&Bl[n * ASTRIDE + c];
                unsigned bl1 = *(const unsigned*)&Bl[n * ASTRIDE + c + 8];
                #pragma unroll
                for (int mt = 0; mt < 2; mt++) {
                    mma16816(acc[mt][nt], ah[mt], bh0, bh1);
                    mma16816(acc[mt][nt], ah[mt], bl0, bl1);
                    mma16816(acc[mt][nt], al[mt], bh0, bh1);
                }
            }
        }
        __syncthreads();
    }

    // ---- epilogue: split hi/lo and write DIRECTLY into attention layouts ----
    #pragma unroll
    for (int mt = 0; mt < 2; mt++)
        #pragma unroll
        for (int nt = 0; nt < 12; nt++) {
            int r0 = wm + mt * 16 + g;
            int n = wn + nt * 8 + ctg * 2;
            #pragma unroll
            for (int half = 0; half < 2; half++) {
                int r = half ? (r0 + 8) : r0;
                float c0 = acc[mt][nt][half * 2 + 0];
                float c1 = acc[mt][nt][half * 2 + 1];
                __nv_bfloat162 h2 = __floats2bfloat162_rn(c0, c1);
                __nv_bfloat162 l2 = __floats2bfloat162_rn(c0 - __low2float(h2),
                                                          c1 - __high2float(h2));
                if (n < 64) {
                    *(__nv_bfloat162*)&Qh[r * QSTR + n] = h2;
                    *(__nv_bfloat162*)&Ql[r * QSTR + n] = l2;
                } else if (n < 128) {
                    *(__nv_bfloat162*)&Kh[r * QSTR + (n - 64)] = h2;
                    *(__nv_bfloat162*)&Kl[r * QSTR + (n - 64)] = l2;
                } else {
                    int h = n - 128;
                    Vh[h * VSTR + r]       = h2.x;
                    Vh[(h + 1) * VSTR + r] = h2.y;
                    Vl[h * VSTR + r]       = l2.x;
                    Vl[(h + 1) * VSTR + r] = l2.y;
                }
            }
        }
    __syncthreads();

    // ======================= Phase 2: attention =======================
    const int am0 = warp * 16;
    const int ntmax = 2 * warp + 1;
    const float scale = 0.40824829046386301636f;   // 6^-0.5
    const float NEG = -1e30f;

    float S[16][4];
    #pragma unroll
    for (int nt = 0; nt < 16; nt++)
        #pragma unroll
        for (int j = 0; j < 4; j++) S[nt][j] = 0.f;

    #pragma unroll 1
    for (int kt = 0; kt < 4; kt++) {
        const int kc = kt * 16 + ctg * 2;
        unsigned ah[4], al[4];
        ah[0] = *(const unsigned*)&Qh[(am0 + g) * QSTR + kc];
        ah[1] = *(const unsigned*)&Qh[(am0 + 8 + g) * QSTR + kc];
        ah[2] = *(const unsigned*)&Qh[(am0 + g) * QSTR + kc + 8];
        ah[3] = *(const unsigned*)&Qh[(am0 + 8 + g) * QSTR + kc + 8];
        al[0] = *(const unsigned*)&Ql[(am0 + g) * QSTR + kc];
        al[1] = *(const unsigned*)&Ql[(am0 + 8 + g) * QSTR + kc];
        al[2] = *(const unsigned*)&Ql[(am0 + g) * QSTR + kc + 8];
        al[3] = *(const unsigned*)&Ql[(am0 + 8 + g) * QSTR + kc + 8];
        #pragma unroll
        for (int nt = 0; nt < 16; nt++) {
            if (nt <= ntmax) {
                unsigned bh0 = *(const unsigned*)&Kh[(nt * 8 + g) * QSTR + kc];
                unsigned bh1 = *(const unsigned*)&Kh[(nt * 8 + g) * QSTR + kc + 8];
                unsigned bl0 = *(const unsigned*)&Kl[(nt * 8 + g) * QSTR + kc];
                unsigned bl1 = *(const unsigned*)&Kl[(nt * 8 + g) * QSTR + kc + 8];
                mma16816(S[nt], ah, bh0, bh1);
                mma16816(S[nt], ah, bl0, bl1);
                mma16816(S[nt], al, bh0, bh1);
            }
        }
    }

    const int t1 = am0 + g, t2 = am0 + 8 + g;
    float mx1 = NEG, mx2 = NEG;
    #pragma unroll
    for (int nt = 0; nt < 16; nt++) {
        if (nt <= ntmax) {
            int s0 = nt * 8 + ctg * 2;
            S[nt][0] = (s0     <= t1) ? S[nt][0] * scale : NEG;
            S[nt][1] = (s0 + 1 <= t1) ? S[nt][1] * scale : NEG;
            S[nt][2] = (s0     <= t2) ? S[nt][2] * scale : NEG;
            S[nt][3] = (s0 + 1 <= t2) ? S[nt][3] * scale : NEG;
            mx1 = fmaxf(mx1, fmaxf(S[nt][0], S[nt][1]));
            mx2 = fmaxf(mx2, fmaxf(S[nt][2], S[nt][3]));
        }
    }
    mx1 = fmaxf(mx1, __shfl_xor_sync(0xffffffffu, mx1, 1));
    mx1 = fmaxf(mx1, __shfl_xor_sync(0xffffffffu, mx1, 2));
    mx2 = fmaxf(mx2, __shfl_xor_sync(0xffffffffu, mx2, 1));
    mx2 = fmaxf(mx2, __shfl_xor_sync(0xffffffffu, mx2, 2));

    float sum1 = 0.f, sum2 = 0.f;
    #pragma unroll
    for (int nt = 0; nt < 16; nt++) {
        if (nt <= ntmax) {
            S[nt][0] = __expf(S[nt][0] - mx1);
            S[nt][1] = __expf(S[nt][1] - mx1);
            S[nt][2] = __expf(S[nt][2] - mx2);
            S[nt][3] = __expf(S[nt][3] - mx2);
            sum1 += S[nt][0] + S[nt][1];
            sum2 += S[nt][2] + S[nt][3];
        }
    }
    sum1 += __shfl_xor_sync(0xffffffffu, sum1, 1);
    sum1 += __shfl_xor_sync(0xffffffffu, sum1, 2);
    sum2 += __shfl_xor_sync(0xffffffffu, sum2, 1);
    sum2 += __shfl_xor_sync(0xffffffffu, sum2, 2);
    const float inv1 = __frcp_rn(sum1), inv2 = __frcp_rn(sum2);

    // pre-normalize weights in place (masked entries are exactly 0)
    #pragma unroll
    for (int nt = 0; nt < 16; nt++) {
        if (nt <= ntmax) {
            S[nt][0] *= inv1;
            S[nt][1] *= inv1;
            S[nt][2] *= inv2;
            S[nt][3] *= inv2;
        }
    }

    float O[8][4];
    #pragma unroll
    for (int nt2 = 0; nt2 < 8; nt2++)
        #pragma unroll
        for (int j = 0; j < 4; j++) O[nt2][j] = 0.f;

    // AV: convert W fragments on the fly (no persistent wah/wal arrays)
    #pragma unroll
    for (int kt2 = 0; kt2 < 8; kt2++) {
        if (kt2 <= warp) {
            unsigned wah[4], wal[4];
            __nv_bfloat162 h2, l2;
            h2 = __floats2bfloat162_rn(S[2 * kt2][0], S[2 * kt2][1]);
            l2 = __floats2bfloat162_rn(S[2 * kt2][0] - __low2float(h2),
                                       S[2 * kt2][1] - __high2float(h2));
            wah[0] = *(unsigned*)&h2; wal[0] = *(unsigned*)&l2;
            h2 = __floats2bfloat162_rn(S[2 * kt2][2], S[2 * kt2][3]);
            l2 = __floats2bfloat162_rn(S[2 * kt2][2] - __low2float(h2),
                                       S[2 * kt2][3] - __high2float(h2));
            wah[1] = *(unsigned*)&h2; wal[1] = *(unsigned*)&l2;
            h2 = __floats2bfloat162_rn(S[2 * kt2 + 1][0], S[2 * kt2 + 1][1]);
            l2 = __floats2bfloat162_rn(S[2 * kt2 + 1][0] - __low2float(h2),
                                       S[2 * kt2 + 1][1] - __high2float(h2));
            wah[2] = *(unsigned*)&h2; wal[2] = *(unsigned*)&l2;
            h2 = __floats2bfloat162_rn(S[2 * kt2 + 1][2], S[2 * kt2 + 1][3]);
            l2 = __floats2bfloat162_rn(S[2 * kt2 + 1][2] - __low2float(h2),
                                       S[2 * kt2 + 1][3] - __high2float(h2));
            wah[3] = *(unsigned*)&h2; wal[3] = *(unsigned*)&l2;

            const int kc = kt2 * 16 + ctg * 2;
            #pragma unroll
            for (int nt2 = 0; nt2 < 8; nt2++) {
                unsigned bh0 = *(const unsigned*)&Vh[(nt2 * 8 + g) * VSTR + kc];
                unsigned bh1 = *(const unsigned*)&Vh[(nt2 * 8 + g) * VSTR + kc + 8];
                unsigned bl0 = *(const unsigned*)&Vl[(nt2 * 8 + g) * VSTR + kc];
                unsigned bl1 = *(const unsigned*)&Vl[(nt2 * 8 + g) * VSTR + kc + 8];
                mma16816(O[nt2], wah, bh0, bh1);
                mma16816(O[nt2], wah, bl0, bl1);
                mma16816(O[nt2], wal, bh0, bh1);
            }
        }
    }

    float* ob = out + (size_t)b * T_DIM * H_DIM;
    #pragma unroll
    for (int nt2 = 0; nt2 < 8; nt2++) {
        int h0 = nt2 * 8 + ctg * 2;
        *(float2*)(ob + (size_t)t1 * H_DIM + h0) = make_float2(O[nt2][0], O[nt2][1]);
        *(float2*)(ob + (size_t)t2 * H_DIM + h0) = make_float2(O[nt2][2], O[nt2][3]);
    }
}

// ---------------------------------------------------------------------------
extern "C" void kernel_launch(void* const* d_in, const int* in_sizes, int n_in,
                              void* d_out, int out_size)
{
    const float* x  = (const float*)d_in[0];
    const float* Wq = (const float*)d_in[1];
    const float* Wk = (const float*)d_in[2];
    const float* Wv = (const float*)d_in[3];
    float* out = (float*)d_out;

    wconv_kernel<<<(192 * C_DIM + 255) / 256, 256>>>(Wq, Wk, Wv);

    int fsmem = (4 * 128 * QSTR + 2 * 64 * VSTR) * (int)sizeof(__nv_bfloat16);  // 108544
    cudaFuncSetAttribute(fused_head, cudaFuncAttributeMaxDynamicSharedMemorySize, fsmem);
    fused_head<<<B_DIM, 256, fsmem>>>(x, out);
}